// round 16
// baseline (speedup 1.0000x reference)
#include <cuda_runtime.h>
#include <cuda_bf16.h>
#include <math.h>

// ---------------------------------------------------------------------------
// Problem constants
// ---------------------------------------------------------------------------
#define BB 2
#define NN 2048
#define DD 1024
#define HH 16
#define HD 64
#define MM (BB * NN)
#define ELEMS (MM * DD)

typedef __nv_bfloat16 bf16;

// ---------------------------------------------------------------------------
// Scratch (static device globals; no allocation allowed)
// ---------------------------------------------------------------------------
__device__ bf16  g_xn [ELEMS];
__device__ bf16  g_tmp[4 * DD * DD];   // bf16 Wq1|Wq2|Wk1|Wk2 staging
__device__ bf16  g_q  [ELEMS];
__device__ bf16  g_k  [ELEMS];
__device__ bf16  g_v  [ELEMS];
__device__ bf16  g_ao [ELEMS];
__device__ float g_h  [BB * DD];
__device__ float g_ada[BB * 2 * DD];
__device__ bf16  g_w1 [DD * 3 * DD];   // [1024][3072] = Wq12 | Wk12 | Wv
__device__ bf16  g_wo [DD * DD];       // [1024][1024]

// ---------------------------------------------------------------------------
// PTX helpers (legacy mma.sync path — tcgen05 rejected by this toolchain)
// ---------------------------------------------------------------------------
__device__ __forceinline__ void cp16(void* s, const void* g) {
    unsigned sa = (unsigned)__cvta_generic_to_shared(s);
    asm volatile("cp.async.cg.shared.global [%0], [%1], 16;" :: "r"(sa), "l"(g));
}
#define CP_COMMIT  asm volatile("cp.async.commit_group;")
#define CP_WAIT(n) asm volatile("cp.async.wait_group %0;" :: "n"(n))

__device__ __forceinline__ void ldsm_x4(unsigned& r0, unsigned& r1, unsigned& r2,
                                        unsigned& r3, const void* p) {
    unsigned a = (unsigned)__cvta_generic_to_shared(p);
    asm volatile("ldmatrix.sync.aligned.m8n8.x4.shared.b16 {%0,%1,%2,%3}, [%4];"
                 : "=r"(r0), "=r"(r1), "=r"(r2), "=r"(r3) : "r"(a));
}
__device__ __forceinline__ void ldsm_x4t(unsigned& r0, unsigned& r1, unsigned& r2,
                                         unsigned& r3, const void* p) {
    unsigned a = (unsigned)__cvta_generic_to_shared(p);
    asm volatile("ldmatrix.sync.aligned.m8n8.x4.trans.shared.b16 {%0,%1,%2,%3}, [%4];"
                 : "=r"(r0), "=r"(r1), "=r"(r2), "=r"(r3) : "r"(a));
}
__device__ __forceinline__ void mma_bf16(float* c, const unsigned* a,
                                         const unsigned* b) {
    asm volatile(
        "mma.sync.aligned.m16n8k16.row.col.f32.bf16.bf16.f32 "
        "{%0,%1,%2,%3}, {%4,%5,%6,%7}, {%8,%9}, {%0,%1,%2,%3};"
        : "+f"(c[0]), "+f"(c[1]), "+f"(c[2]), "+f"(c[3])
        : "r"(a[0]), "r"(a[1]), "r"(a[2]), "r"(a[3]), "r"(b[0]), "r"(b[1]));
}
__device__ __forceinline__ unsigned packbf(float a, float b) {
    __nv_bfloat162 t = __floats2bfloat162_rn(a, b);
    return *reinterpret_cast<unsigned*>(&t);
}

// ---------------------------------------------------------------------------
// Pack: Wq1,Wq2,Wk1,Wk2 -> bf16 staging; Wv -> w1 seg2; Wo -> wo. grid(1024,6)
// ---------------------------------------------------------------------------
__global__ void pack_all(const float* __restrict__ Wq1, const float* __restrict__ Wq2,
                         const float* __restrict__ Wk1, const float* __restrict__ Wk2,
                         const float* __restrict__ Wv,  const float* __restrict__ Wo,
                         bf16* __restrict__ tmp, bf16* __restrict__ w1,
                         bf16* __restrict__ wo) {
    const float* src; bf16* dst; int ld, col0;
    switch (blockIdx.y) {
        case 0:  src = Wq1; dst = tmp;                ld = DD;     col0 = 0;      break;
        case 1:  src = Wq2; dst = tmp + 1 * DD * DD;  ld = DD;     col0 = 0;      break;
        case 2:  src = Wk1; dst = tmp + 2 * DD * DD;  ld = DD;     col0 = 0;      break;
        case 3:  src = Wk2; dst = tmp + 3 * DD * DD;  ld = DD;     col0 = 0;      break;
        case 4:  src = Wv;  dst = w1;                 ld = 3 * DD; col0 = 2 * DD; break;
        default: src = Wo;  dst = wo;                 ld = DD;     col0 = 0;      break;
    }
    int idx = blockIdx.x * 256 + threadIdx.x;
    int r = idx >> 8;
    int c = (idx & 255) * 4;
    float4 v = *(const float4*)(src + r * 1024 + c);
    bf16* d = dst + (size_t)r * ld + col0 + c;
    *(__nv_bfloat162*)(d)     = __floats2bfloat162_rn(v.x, v.y);
    *(__nv_bfloat162*)(d + 2) = __floats2bfloat162_rn(v.z, v.w);
}

// ---------------------------------------------------------------------------
// adaLN matvecs, parallelized: 64 outputs/block, 4-way K-split per output.
// fc1: h = silu(emb) @ Wada1            grid (16, 2)
// fc2: ada = h @ Wada2 + bias           grid (32, 2)
// ---------------------------------------------------------------------------
__global__ void ada_fc1(const float* __restrict__ emb, const float* __restrict__ W,
                        float* __restrict__ h) {
    const int b  = blockIdx.y;
    const int o0 = blockIdx.x * 64;
    const int tid = threadIdx.x;
    __shared__ float se[DD];
    __shared__ float part[256];

    for (int i = tid; i < DD; i += 256) {
        float e = emb[b * DD + i];
        se[i] = e / (1.0f + expf(-e));
    }
    __syncthreads();

    const int o  = o0 + (tid & 63);
    const int kq = tid >> 6;                  // 0..3
    const float* wp = W + (size_t)(kq * 256) * DD + o;
    const float* sp = se + kq * 256;
    float acc = 0.0f;
    #pragma unroll 8
    for (int k = 0; k < 256; k++) acc += sp[k] * wp[(size_t)k * DD];
    part[tid] = acc;
    __syncthreads();
    if (tid < 64)
        h[b * DD + o0 + tid] = part[tid] + part[64 + tid] +
                               part[128 + tid] + part[192 + tid];
}

__global__ void ada_fc2(const float* __restrict__ h, const float* __restrict__ W,
                        const float* __restrict__ bias, float* __restrict__ ada) {
    const int b  = blockIdx.y;
    const int o0 = blockIdx.x * 64;
    const int tid = threadIdx.x;
    __shared__ float sh[DD];
    __shared__ float part[256];

    for (int i = tid; i < DD; i += 256) sh[i] = h[b * DD + i];
    __syncthreads();

    const int o  = o0 + (tid & 63);
    const int kq = tid >> 6;
    const float* wp = W + (size_t)(kq * 256) * (2 * DD) + o;
    const float* sp = sh + kq * 256;
    float acc = 0.0f;
    #pragma unroll 8
    for (int k = 0; k < 256; k++) acc += sp[k] * wp[(size_t)k * (2 * DD)];
    part[tid] = acc;
    __syncthreads();
    if (tid < 64)
        ada[b * 2 * DD + o0 + tid] = bias[o0 + tid] + part[tid] + part[64 + tid] +
                                     part[128 + tid] + part[192 + tid];
}

// ---------------------------------------------------------------------------
// LayerNorm + adaLN scale/shift -> bf16
// ---------------------------------------------------------------------------
__global__ void ln_mod(const float* __restrict__ x, const float* __restrict__ ada,
                       bf16* __restrict__ xn) {
    int row = blockIdx.x;
    int b = row >> 11;
    int tid = threadIdx.x;
    const float* xr = x + (size_t)row * DD;

    float4 xv = *(const float4*)(xr + tid * 4);
    float s  = xv.x + xv.y + xv.z + xv.w;
    float s2 = xv.x * xv.x + xv.y * xv.y + xv.z * xv.z + xv.w * xv.w;
    #pragma unroll
    for (int off = 16; off; off >>= 1) {
        s  += __shfl_xor_sync(0xffffffffu, s,  off);
        s2 += __shfl_xor_sync(0xffffffffu, s2, off);
    }
    __shared__ float rs[8], rs2[8];
    int wid = tid >> 5, lane = tid & 31;
    if (lane == 0) { rs[wid] = s; rs2[wid] = s2; }
    __syncthreads();
    float S = 0.f, S2 = 0.f;
    #pragma unroll
    for (int w = 0; w < 8; w++) { S += rs[w]; S2 += rs2[w]; }
    float mu  = S * (1.0f / DD);
    float var = S2 * (1.0f / DD) - mu * mu;
    float rinv = rsqrtf(var + 1e-6f);

    int c = tid * 4;
    float4 sc  = *(const float4*)(ada + b * 2 * DD + DD + c);
    float4 shv = *(const float4*)(ada + b * 2 * DD + c);
    float o0 = (xv.x - mu) * rinv * (1.0f + sc.x) + shv.x;
    float o1 = (xv.y - mu) * rinv * (1.0f + sc.y) + shv.y;
    float o2 = (xv.z - mu) * rinv * (1.0f + sc.z) + shv.z;
    float o3 = (xv.w - mu) * rinv * (1.0f + sc.w) + shv.w;
    uint2 st;
    st.x = packbf(o0, o1);
    st.y = packbf(o2, o3);
    *(uint2*)(xn + (size_t)row * DD + c) = st;
}

// ---------------------------------------------------------------------------
// Shared GEMM tile parameters
// ---------------------------------------------------------------------------
#define ASTR 40    // halves: 32 + 8 pad
#define BSTR 136   // halves: 128 + 8 pad
#define GSTAGES 4
#define GEMM_SMEM (GSTAGES * (128 * ASTR + 32 * BSTR) * 2)

// ---------------------------------------------------------------------------
// Weight-combine GEMM: Wq12 = bWq1 @ bWq2, Wk12 = bWk1 @ bWk2  (M=N=K=1024)
// grid (16, 8): mat = bx>>3 (0:q, 1:k), output into w1 segs 0/1 (ld 3072).
// ---------------------------------------------------------------------------
__global__ __launch_bounds__(256, 2)
void wgemm(const bf16* __restrict__ T, bf16* __restrict__ w1) {
    extern __shared__ bf16 smg[];
    bf16* Asm = smg;
    bf16* Bsm = smg + GSTAGES * 128 * ASTR;

    const int mat  = blockIdx.x >> 3;
    const int coln = (blockIdx.x & 7) * 128;
    const int bm   = blockIdx.y * 128;
    const bf16* A = T + (size_t)mat * 2 * DD * DD;            // Wq1 or Wk1
    const bf16* B = T + (size_t)mat * 2 * DD * DD + DD * DD;  // Wq2 or Wk2

    const int tid = threadIdx.x;
    const int warp = tid >> 5, lane = tid & 31;
    const int gid = lane >> 2, tig = lane & 3;
    const int wm = (warp >> 2) * 64;
    const int wn = (warp & 3) * 32;

    float acc[4][4][4];
    #pragma unroll
    for (int mi = 0; mi < 4; mi++)
        #pragma unroll
        for (int ni = 0; ni < 4; ni++)
            #pragma unroll
            for (int r = 0; r < 4; r++) acc[mi][ni][r] = 0.0f;

    auto issue = [&](int st, int k0) {
        bf16* as = Asm + st * 128 * ASTR;
        bf16* bs = Bsm + st * 32 * BSTR;
        #pragma unroll
        for (int i = 0; i < 2; i++) {
            int idx = tid + i * 256;
            int ar = idx >> 2, ach = idx & 3;
            cp16(&as[ar * ASTR + ach * 8],
                 &A[(size_t)(bm + ar) * DD + k0 + ach * 8]);
            int br = idx >> 4, bch = idx & 15;
            cp16(&bs[br * BSTR + bch * 8],
                 &B[(size_t)(k0 + br) * DD + coln + bch * 8]);
        }
    };

    #pragma unroll
    for (int s = 0; s < 3; s++) { issue(s, s * 32); CP_COMMIT; }

    for (int kt = 0; kt < DD / 32; kt++) {
        CP_WAIT(2);
        __syncthreads();
        if (kt + 3 < DD / 32) issue((kt + 3) & 3, (kt + 3) * 32);
        CP_COMMIT;

        const bf16* as = Asm + (kt & 3) * 128 * ASTR;
        const bf16* bs = Bsm + (kt & 3) * 32 * BSTR;
        #pragma unroll
        for (int kk = 0; kk < 2; kk++) {
            unsigned af[4][4], bfg[4][2];
            #pragma unroll
            for (int mi = 0; mi < 4; mi++) {
                int row = wm + mi * 16 + (lane & 15);
                int col = kk * 16 + 8 * (lane >> 4);
                ldsm_x4(af[mi][0], af[mi][1], af[mi][2], af[mi][3],
                        &as[row * ASTR + col]);
            }
            #pragma unroll
            for (int nj = 0; nj < 2; nj++) {
                int row = kk * 16 + (lane & 7) + 8 * ((lane >> 3) & 1);
                int col = wn + nj * 16 + 8 * (lane >> 4);
                unsigned r0, r1, r2, r3;
                ldsm_x4t(r0, r1, r2, r3, &bs[row * BSTR + col]);
                bfg[nj * 2][0] = r0; bfg[nj * 2][1] = r1;
                bfg[nj * 2 + 1][0] = r2; bfg[nj * 2 + 1][1] = r3;
            }
            #pragma unroll
            for (int mi = 0; mi < 4; mi++)
                #pragma unroll
                for (int ni = 0; ni < 4; ni++)
                    mma_bf16(acc[mi][ni], af[mi], bfg[ni]);
        }
    }

    bf16* dst = w1 + (size_t)mat * DD;   // seg column offset in [1024][3072]
    #pragma unroll
    for (int mi = 0; mi < 4; mi++) {
        #pragma unroll
        for (int ni = 0; ni < 4; ni++) {
            int col = coln + wn + ni * 8 + 2 * tig;
            #pragma unroll
            for (int half = 0; half < 2; half++) {
                int row = bm + wm + mi * 16 + gid + half * 8;
                *(unsigned*)(dst + (size_t)row * (3 * DD) + col) =
                    packbf(acc[mi][ni][half * 2], acc[mi][ni][half * 2 + 1]);
            }
        }
    }
}

// ---------------------------------------------------------------------------
// Fused QKV GEMM + RoPE: [q|k|v] = xn @ [Wq12|Wk12|Wv], RoPE on q/k segs.
// grid (24, 32). Warp tile 32x64 (head-aligned).
// ---------------------------------------------------------------------------
__global__ __launch_bounds__(256, 2)
void qkv_rope(const bf16* __restrict__ A, const bf16* __restrict__ B,
              const float* __restrict__ rope,
              bf16* __restrict__ Cq, bf16* __restrict__ Ck,
              bf16* __restrict__ Cv) {
    extern __shared__ bf16 smg[];
    bf16* Asm = smg;
    bf16* Bsm = smg + GSTAGES * 128 * ASTR;

    const int bm = blockIdx.y * 128;
    const int bn = blockIdx.x * 128;
    const int seg = bn >> 10;
    const int coln = bn & 1023;

    const int tid = threadIdx.x;
    const int warp = tid >> 5, lane = tid & 31;
    const int gid = lane >> 2, tig = lane & 3;
    const int wm = (warp & 3) * 32;    // 4 row groups of 32
    const int wn = (warp >> 2) * 64;   // 2 col groups of 64 (head-aligned)

    float acc[2][8][4];
    #pragma unroll
    for (int mi = 0; mi < 2; mi++)
        #pragma unroll
        for (int ni = 0; ni < 8; ni++)
            #pragma unroll
            for (int r = 0; r < 4; r++) acc[mi][ni][r] = 0.0f;

    auto issue = [&](int st, int k0) {
        bf16* as = Asm + st * 128 * ASTR;
        bf16* bs = Bsm + st * 32 * BSTR;
        #pragma unroll
        for (int i = 0; i < 2; i++) {
            int idx = tid + i * 256;
            int ar = idx >> 2, ach = idx & 3;
            cp16(&as[ar * ASTR + ach * 8],
                 &A[(size_t)(bm + ar) * DD + k0 + ach * 8]);
            int br = idx >> 4, bch = idx & 15;
            cp16(&bs[br * BSTR + bch * 8],
                 &B[(size_t)(k0 + br) * (3 * DD) + bn + bch * 8]);
        }
    };

    #pragma unroll
    for (int s = 0; s < 3; s++) { issue(s, s * 32); CP_COMMIT; }

    for (int kt = 0; kt < DD / 32; kt++) {
        CP_WAIT(2);
        __syncthreads();
        if (kt + 3 < DD / 32) issue((kt + 3) & 3, (kt + 3) * 32);
        CP_COMMIT;

        const bf16* as = Asm + (kt & 3) * 128 * ASTR;
        const bf16* bs = Bsm + (kt & 3) * 32 * BSTR;
        #pragma unroll
        for (int kk = 0; kk < 2; kk++) {
            unsigned af[2][4], bfg[8][2];
            #pragma unroll
            for (int mi = 0; mi < 2; mi++) {
                int row = wm + mi * 16 + (lane & 15);
                int col = kk * 16 + 8 * (lane >> 4);
                ldsm_x4(af[mi][0], af[mi][1], af[mi][2], af[mi][3],
                        &as[row * ASTR + col]);
            }
            #pragma unroll
            for (int nj = 0; nj < 4; nj++) {
                int row = kk * 16 + (lane & 7) + 8 * ((lane >> 3) & 1);
                int col = wn + nj * 16 + 8 * (lane >> 4);
                unsigned r0, r1, r2, r3;
                ldsm_x4t(r0, r1, r2, r3, &bs[row * BSTR + col]);
                bfg[nj * 2][0] = r0; bfg[nj * 2][1] = r1;
                bfg[nj * 2 + 1][0] = r2; bfg[nj * 2 + 1][1] = r3;
            }
            #pragma unroll
            for (int mi = 0; mi < 2; mi++)
                #pragma unroll
                for (int ni = 0; ni < 8; ni++)
                    mma_bf16(acc[mi][ni], af[mi], bfg[ni]);
        }
    }

    if (seg == 2) {
        #pragma unroll
        for (int mi = 0; mi < 2; mi++) {
            #pragma unroll
            for (int ni = 0; ni < 8; ni++) {
                int col = coln + wn + ni * 8 + 2 * tig;
                #pragma unroll
                for (int half = 0; half < 2; half++) {
                    int row = bm + wm + mi * 16 + gid + half * 8;
                    *(unsigned*)(Cv + (size_t)row * DD + col) =
                        packbf(acc[mi][ni][half * 2], acc[mi][ni][half * 2 + 1]);
                }
            }
        }
    } else {
        bf16* Cb = (seg == 0) ? Cq : Ck;
        #pragma unroll
        for (int mi = 0; mi < 2; mi++) {
            #pragma unroll
            for (int half = 0; half < 2; half++) {
                int row = bm + wm + mi * 16 + gid + half * 8;
                int n = row & (NN - 1);
                const float* rp = rope + (size_t)n * HD;
                #pragma unroll
                for (int ni = 0; ni < 4; ni++) {
                    int d0 = ni * 8 + 2 * tig;     // in-head index < 32
                    float lo0 = acc[mi][ni][half * 2 + 0];
                    float lo1 = acc[mi][ni][half * 2 + 1];
                    float hi0 = acc[mi][ni + 4][half * 2 + 0];
                    float hi1 = acc[mi][ni + 4][half * 2 + 1];
                    float c10, s10, c11, s11, c20, s20, c21, s21;
                    __sincosf(rp[d0],      &s10, &c10);
                    __sincosf(rp[d0 + 1],  &s11, &c11);
                    __sincosf(rp[d0 + 32], &s20, &c20);
                    __sincosf(rp[d0 + 33], &s21, &c21);
                    float q_lo0 = lo0 * c10 - hi0 * s10;
                    float q_lo1 = lo1 * c11 - hi1 * s11;
                    float q_hi0 = hi0 * c20 + lo0 * s20;
                    float q_hi1 = hi1 * c21 + lo1 * s21;
                    int gc = coln + wn + d0;
                    *(unsigned*)(Cb + (size_t)row * DD + gc)      = packbf(q_lo0, q_lo1);
                    *(unsigned*)(Cb + (size_t)row * DD + gc + 32) = packbf(q_hi0, q_hi1);
                }
            }
        }
    }
}

// ---------------------------------------------------------------------------
// Output GEMM: out = x + gate * (ao @ Wo).  64x32 warp tiles, fp32 epilogue.
// ---------------------------------------------------------------------------
__global__ __launch_bounds__(256, 2)
void tgemm_out(const bf16* __restrict__ A, const bf16* __restrict__ B,
               float* __restrict__ Cf, const float* __restrict__ X,
               const float* __restrict__ gate) {
    extern __shared__ bf16 smg[];
    bf16* Asm = smg;
    bf16* Bsm = smg + GSTAGES * 128 * ASTR;

    const int bm = blockIdx.y * 128;
    const int bn = blockIdx.x * 128;

    const int tid = threadIdx.x;
    const int warp = tid >> 5, lane = tid & 31;
    const int gid = lane >> 2, tig = lane & 3;
    const int wm = (warp >> 2) * 64;
    const int wn = (warp & 3) * 32;

    float acc[4][4][4];
    #pragma unroll
    for (int mi = 0; mi < 4; mi++)
        #pragma unroll
        for (int ni = 0; ni < 4; ni++)
            #pragma unroll
            for (int r = 0; r < 4; r++) acc[mi][ni][r] = 0.0f;

    auto issue = [&](int st, int k0) {
        bf16* as = Asm + st * 128 * ASTR;
        bf16* bs = Bsm + st * 32 * BSTR;
        #pragma unroll
        for (int i = 0; i < 2; i++) {
            int idx = tid + i * 256;
            int ar = idx >> 2, ach = idx & 3;
            cp16(&as[ar * ASTR + ach * 8],
                 &A[(size_t)(bm + ar) * DD + k0 + ach * 8]);
            int br = idx >> 4, bch = idx & 15;
            cp16(&bs[br * BSTR + bch * 8],
                 &B[(size_t)(k0 + br) * DD + bn + bch * 8]);
        }
    };

    #pragma unroll
    for (int s = 0; s < 3; s++) { issue(s, s * 32); CP_COMMIT; }

    for (int kt = 0; kt < DD / 32; kt++) {
        CP_WAIT(2);
        __syncthreads();
        if (kt + 3 < DD / 32) issue((kt + 3) & 3, (kt + 3) * 32);
        CP_COMMIT;

        const bf16* as = Asm + (kt & 3) * 128 * ASTR;
        const bf16* bs = Bsm + (kt & 3) * 32 * BSTR;
        #pragma unroll
        for (int kk = 0; kk < 2; kk++) {
            unsigned af[4][4], bfg[4][2];
            #pragma unroll
            for (int mi = 0; mi < 4; mi++) {
                int row = wm + mi * 16 + (lane & 15);
                int col = kk * 16 + 8 * (lane >> 4);
                ldsm_x4(af[mi][0], af[mi][1], af[mi][2], af[mi][3],
                        &as[row * ASTR + col]);
            }
            #pragma unroll
            for (int nj = 0; nj < 2; nj++) {
                int row = kk * 16 + (lane & 7) + 8 * ((lane >> 3) & 1);
                int col = wn + nj * 16 + 8 * (lane >> 4);
                unsigned r0, r1, r2, r3;
                ldsm_x4t(r0, r1, r2, r3, &bs[row * BSTR + col]);
                bfg[nj * 2][0] = r0; bfg[nj * 2][1] = r1;
                bfg[nj * 2 + 1][0] = r2; bfg[nj * 2 + 1][1] = r3;
            }
            #pragma unroll
            for (int mi = 0; mi < 4; mi++)
                #pragma unroll
                for (int ni = 0; ni < 4; ni++)
                    mma_bf16(acc[mi][ni], af[mi], bfg[ni]);
        }
    }

    #pragma unroll
    for (int mi = 0; mi < 4; mi++) {
        #pragma unroll
        for (int ni = 0; ni < 4; ni++) {
            int col = bn + wn + ni * 8 + 2 * tig;
            #pragma unroll
            for (int half = 0; half < 2; half++) {
                int row = bm + wm + mi * 16 + gid + half * 8;
                int bidx = row >> 11;
                float2 xv = *(const float2*)(X + (size_t)row * DD + col);
                float2 gv = *(const float2*)(gate + bidx * DD + col);
                float2 r;
                r.x = xv.x + gv.x * acc[mi][ni][half * 2 + 0];
                r.y = xv.y + gv.y * acc[mi][ni][half * 2 + 1];
                *(float2*)(Cf + (size_t)row * DD + col) = r;
            }
        }
    }
}

// ---------------------------------------------------------------------------
// Flash attention, bf16 mma. grid (N/128, H, B), 256 threads (8 warps).
// 128-row Q tile, 3-stage KV ring, P in registers, exp2 softmax with
// skip-rescale when the running max is unchanged.
// ---------------------------------------------------------------------------
#define QSTR 72
#define ATTN_SMEM ((128 * QSTR + 6 * 64 * QSTR) * 2)
#define SOFTMAX_SCALE 0.18033688f   // 0.125 * log2(e)

__global__ __launch_bounds__(256, 2)
void attn_kernel(const bf16* __restrict__ q, const bf16* __restrict__ k,
                 const bf16* __restrict__ v, bf16* __restrict__ o) {
    extern __shared__ bf16 sma[];
    bf16* Qs  = sma;
    bf16* KVs = sma + 128 * QSTR;

    const int qt = blockIdx.x, h = blockIdx.y, b = blockIdx.z;
    const int tid = threadIdx.x;
    const int warp = tid >> 5, lane = tid & 31;
    const int gid = lane >> 2, tig = lane & 3;
    const int hoff = h * HD;
    const size_t bbase = (size_t)b * NN * DD;

    auto issue_kv = [&](int kt, int st) {
        bf16* Ks = KVs + st * 2 * 64 * QSTR;
        bf16* Vs = Ks + 64 * QSTR;
        #pragma unroll
        for (int i = 0; i < 2; i++) {
            int idx = tid + i * 256;
            int r = idx >> 3, ch = idx & 7;
            size_t g = bbase + (size_t)(kt * 64 + r) * DD + hoff + ch * 8;
            cp16(&Ks[r * QSTR + ch * 8], &k[g]);
            cp16(&Vs[r * QSTR + ch * 8], &v[g]);
        }
    };

    #pragma unroll
    for (int i = 0; i < 4; i++) {
        int idx = tid + i * 256;
        int r = idx >> 3, ch = idx & 7;
        cp16(&Qs[r * QSTR + ch * 8],
             &q[bbase + (size_t)(qt * 128 + r) * DD + hoff + ch * 8]);
    }
    issue_kv(0, 0);
    CP_COMMIT;
    issue_kv(1, 1);
    CP_COMMIT;

    unsigned qa[4][4];
    float m_i[2] = {-1e30f, -1e30f};
    float l_i[2] = {0.0f, 0.0f};
    float O[8][4];
    #pragma unroll
    for (int ni = 0; ni < 8; ni++)
        #pragma unroll
        for (int r = 0; r < 4; r++) O[ni][r] = 0.0f;

    for (int kt = 0; kt < NN / 64; kt++) {
        CP_WAIT(1);
        __syncthreads();
        if (kt + 2 < NN / 64) issue_kv(kt + 2, (kt + 2) % 3);
        CP_COMMIT;

        if (kt == 0) {
            #pragma unroll
            for (int kk = 0; kk < 4; kk++) {
                int row = warp * 16 + (lane & 15);
                int col = kk * 16 + 8 * (lane >> 4);
                ldsm_x4(qa[kk][0], qa[kk][1], qa[kk][2], qa[kk][3],
                        &Qs[row * QSTR + col]);
            }
        }

        const bf16* ks = KVs + (kt % 3) * 2 * 64 * QSTR;
        const bf16* vs = ks + 64 * QSTR;

        float S[8][4];
        #pragma unroll
        for (int ni = 0; ni < 8; ni++)
            #pragma unroll
            for (int r = 0; r < 4; r++) S[ni][r] = 0.0f;
        #pragma unroll
        for (int kk = 0; kk < 4; kk++) {
            #pragma unroll
            for (int nj = 0; nj < 4; nj++) {
                int row = nj * 16 + (lane & 7) + 8 * (lane >> 4);
                int col = kk * 16 + 8 * ((lane >> 3) & 1);
                unsigned r0, r1, r2, r3;
                ldsm_x4(r0, r1, r2, r3, &ks[row * QSTR + col]);
                unsigned b0[2] = {r0, r1}, b1[2] = {r2, r3};
                mma_bf16(S[nj * 2],     qa[kk], b0);
                mma_bf16(S[nj * 2 + 1], qa[kk], b1);
            }
        }
        #pragma unroll
        for (int ni = 0; ni < 8; ni++)
            #pragma unroll
            for (int r = 0; r < 4; r++) S[ni][r] *= SOFTMAX_SCALE;

        // online softmax in exp2 domain; skip O-rescale when max unchanged
        #pragma unroll
        for (int half = 0; half < 2; half++) {
            float mx = -1e30f;
            #pragma unroll
            for (int ni = 0; ni < 8; ni++)
                mx = fmaxf(mx, fmaxf(S[ni][half * 2], S[ni][half * 2 + 1]));
            mx = fmaxf(mx, __shfl_xor_sync(0xffffffffu, mx, 1));
            mx = fmaxf(mx, __shfl_xor_sync(0xffffffffu, mx, 2));
            float fac = 1.0f;
            if (mx > m_i[half]) {
                fac = exp2f(m_i[half] - mx);
                m_i[half] = mx;
                #pragma unroll
                for (int ni = 0; ni < 8; ni++) {
                    O[ni][half * 2]     *= fac;
                    O[ni][half * 2 + 1] *= fac;
                }
            }
            float mnew = m_i[half];
            float rs = 0.0f;
            #pragma unroll
            for (int ni = 0; ni < 8; ni++) {
                float p0 = exp2f(S[ni][half * 2]     - mnew);
                float p1 = exp2f(S[ni][half * 2 + 1] - mnew);
                S[ni][half * 2]     = p0;
                S[ni][half * 2 + 1] = p1;
                rs += p0 + p1;
            }
            rs += __shfl_xor_sync(0xffffffffu, rs, 1);
            rs += __shfl_xor_sync(0xffffffffu, rs, 2);
            l_i[half] = l_i[half] * fac + rs;
        }

        unsigned pa[4][4];
        #pragma unroll
        for (int kk2 = 0; kk2 < 4; kk2++) {
            pa[kk2][0] = packbf(S[2 * kk2][0],     S[2 * kk2][1]);
            pa[kk2][1] = packbf(S[2 * kk2][2],     S[2 * kk2][3]);
            pa[kk2][2] = packbf(S[2 * kk2 + 1][0], S[2 * kk2 + 1][1]);
            pa[kk2][3] = packbf(S[2 * kk2 + 1][2], S[2 * kk2 + 1][3]);
        }

        #pragma unroll
        for (int kk2 = 0; kk2 < 4; kk2++) {
            #pragma unroll
            for (int nj = 0; nj < 4; nj++) {
                int row = kk2 * 16 + (lane & 7) + 8 * ((lane >> 3) & 1);
                int col = nj * 16 + 8 * (lane >> 4);
                unsigned r0, r1, r2, r3;
                ldsm_x4t(r0, r1, r2, r3, &vs[row * QSTR + col]);
                unsigned b0[2] = {r0, r1}, b1[2] = {r2, r3};
                mma_bf16(O[nj * 2],     pa[kk2], b0);
                mma_bf16(O[nj * 2 + 1], pa[kk2], b1);
            }
        }
    }

    float inv0 = 1.0f / l_i[0], inv1 = 1.0f / l_i[1];
    #pragma unroll
    for (int ni = 0; ni < 8; ni++) {
        int col = hoff + ni * 8 + 2 * tig;
        int row0 = qt * 128 + warp * 16 + gid;
        *(unsigned*)(o + bbase + (size_t)row0 * DD + col) =
            packbf(O[ni][0] * inv0, O[ni][1] * inv0);
        *(unsigned*)(o + bbase + (size_t)(row0 + 8) * DD + col) =
            packbf(O[ni][2] * inv1, O[ni][3] * inv1);
    }
}

// ---------------------------------------------------------------------------
// Launcher
// ---------------------------------------------------------------------------
extern "C" void kernel_launch(void* const* d_in, const int* in_sizes, int n_in,
                              void* d_out, int out_size) {
    const float* x     = (const float*)d_in[0];
    const float* emb   = (const float*)d_in[1];
    const float* gate  = (const float*)d_in[2];
    // d_in[3] = crossattn_emb: unused by the reference
    const float* rope  = (const float*)d_in[4];
    const float* Wq1   = (const float*)d_in[5];
    const float* Wq2   = (const float*)d_in[6];
    const float* Wk1   = (const float*)d_in[7];
    const float* Wk2   = (const float*)d_in[8];
    const float* Wv    = (const float*)d_in[9];
    const float* Wo    = (const float*)d_in[10];
    const float* Wada1 = (const float*)d_in[11];
    const float* Wada2 = (const float*)d_in[12];
    const float* bada2 = (const float*)d_in[13];
    float* out = (float*)d_out;

    bf16 *xn_p, *tmp_p, *q_p, *k_p, *v_p, *ao_p, *w1_p, *wo_p;
    float *h_p, *ada_p;
    cudaGetSymbolAddress((void**)&xn_p,  g_xn);
    cudaGetSymbolAddress((void**)&tmp_p, g_tmp);
    cudaGetSymbolAddress((void**)&q_p,   g_q);
    cudaGetSymbolAddress((void**)&k_p,   g_k);
    cudaGetSymbolAddress((void**)&v_p,   g_v);
    cudaGetSymbolAddress((void**)&ao_p,  g_ao);
    cudaGetSymbolAddress((void**)&h_p,   g_h);
    cudaGetSymbolAddress((void**)&ada_p, g_ada);
    cudaGetSymbolAddress((void**)&w1_p,  g_w1);
    cudaGetSymbolAddress((void**)&wo_p,  g_wo);

    cudaFuncSetAttribute(wgemm,     cudaFuncAttributeMaxDynamicSharedMemorySize, GEMM_SMEM);
    cudaFuncSetAttribute(qkv_rope,  cudaFuncAttributeMaxDynamicSharedMemorySize, GEMM_SMEM);
    cudaFuncSetAttribute(tgemm_out, cudaFuncAttributeMaxDynamicSharedMemorySize, GEMM_SMEM);
    cudaFuncSetAttribute(attn_kernel, cudaFuncAttributeMaxDynamicSharedMemorySize, ATTN_SMEM);

    // adaLN modulation (parallelized matvecs) — launched first so they
    // overlap nothing critical and ln_mod's dependency is satisfied early
    ada_fc1<<<dim3(16, 2), 256>>>(emb, Wada1, h_p);
    ada_fc2<<<dim3(32, 2), 256>>>(h_p, Wada2, bada2, ada_p);

    // pack weights -> bf16 staging (+ Wv, Wo into final layouts)
    pack_all<<<dim3(1024, 6), 256>>>(Wq1, Wq2, Wk1, Wk2, Wv, Wo,
                                     tmp_p, w1_p, wo_p);

    // combine stacked projections: w1 seg0 = Wq1@Wq2, seg1 = Wk1@Wk2
    wgemm<<<dim3(16, 8), 256, GEMM_SMEM>>>(tmp_p, w1_p);

    // LayerNorm + scale/shift -> bf16
    ln_mod<<<MM, 256>>>(x, ada_p, xn_p);

    // Fused QKV projection + RoPE: [q|k|v] = xn @ [Wq12|Wk12|Wv]
    qkv_rope<<<dim3(24, 32), 256, GEMM_SMEM>>>(xn_p, w1_p, rope,
                                               q_p, k_p, v_p);

    // Attention (128-row Q tiles, 3-stage KV pipeline, 2 CTAs/SM)
    attn_kernel<<<dim3(NN / 128, HH, BB), 256, ATTN_SMEM>>>(q_p, k_p, v_p, ao_p);

    // Output GEMM: out = x + gate * (ao @ Wo)
    tgemm_out<<<dim3(8, 32), 256, GEMM_SMEM>>>(ao_p, wo_p, out, x, gate);
}

// round 17
// speedup vs baseline: 1.5668x; 1.5668x over previous
#include <cuda_runtime.h>
#include <cuda_bf16.h>
#include <math.h>

// ---------------------------------------------------------------------------
// Problem constants
// ---------------------------------------------------------------------------
#define BB 2
#define NN 2048
#define DD 1024
#define HH 16
#define HD 64
#define MM (BB * NN)
#define ELEMS (MM * DD)

typedef __nv_bfloat16 bf16;

// ---------------------------------------------------------------------------
// Scratch (static device globals; no allocation allowed)
// ---------------------------------------------------------------------------
__device__ bf16  g_xn [ELEMS];
__device__ bf16  g_tmp[4 * DD * DD];   // bf16 Wq1|Wq2|Wk1|Wk2 staging
__device__ bf16  g_q  [ELEMS];
__device__ bf16  g_k  [ELEMS];
__device__ bf16  g_v  [ELEMS];
__device__ bf16  g_ao [ELEMS];
__device__ float g_h  [BB * DD];
__device__ float g_ada[BB * 2 * DD];
__device__ bf16  g_w1 [DD * 3 * DD];   // [1024][3072] = Wq12 | Wk12 | Wv
__device__ bf16  g_wo [DD * DD];       // [1024][1024]

// ---------------------------------------------------------------------------
// PTX helpers (legacy mma.sync path — tcgen05 rejected by this toolchain)
// ---------------------------------------------------------------------------
__device__ __forceinline__ void cp16(void* s, const void* g) {
    unsigned sa = (unsigned)__cvta_generic_to_shared(s);
    asm volatile("cp.async.cg.shared.global [%0], [%1], 16;" :: "r"(sa), "l"(g));
}
#define CP_COMMIT  asm volatile("cp.async.commit_group;")
#define CP_WAIT(n) asm volatile("cp.async.wait_group %0;" :: "n"(n))

__device__ __forceinline__ void ldsm_x4(unsigned& r0, unsigned& r1, unsigned& r2,
                                        unsigned& r3, const void* p) {
    unsigned a = (unsigned)__cvta_generic_to_shared(p);
    asm volatile("ldmatrix.sync.aligned.m8n8.x4.shared.b16 {%0,%1,%2,%3}, [%4];"
                 : "=r"(r0), "=r"(r1), "=r"(r2), "=r"(r3) : "r"(a));
}
__device__ __forceinline__ void ldsm_x4t(unsigned& r0, unsigned& r1, unsigned& r2,
                                         unsigned& r3, const void* p) {
    unsigned a = (unsigned)__cvta_generic_to_shared(p);
    asm volatile("ldmatrix.sync.aligned.m8n8.x4.trans.shared.b16 {%0,%1,%2,%3}, [%4];"
                 : "=r"(r0), "=r"(r1), "=r"(r2), "=r"(r3) : "r"(a));
}
__device__ __forceinline__ void mma_bf16(float* c, const unsigned* a,
                                         const unsigned* b) {
    asm volatile(
        "mma.sync.aligned.m16n8k16.row.col.f32.bf16.bf16.f32 "
        "{%0,%1,%2,%3}, {%4,%5,%6,%7}, {%8,%9}, {%0,%1,%2,%3};"
        : "+f"(c[0]), "+f"(c[1]), "+f"(c[2]), "+f"(c[3])
        : "r"(a[0]), "r"(a[1]), "r"(a[2]), "r"(a[3]), "r"(b[0]), "r"(b[1]));
}
__device__ __forceinline__ unsigned packbf(float a, float b) {
    __nv_bfloat162 t = __floats2bfloat162_rn(a, b);
    return *reinterpret_cast<unsigned*>(&t);
}

// ---------------------------------------------------------------------------
// Pack: Wq1,Wq2,Wk1,Wk2 -> bf16 staging; Wv -> w1 seg2; Wo -> wo. grid(1024,6)
// ---------------------------------------------------------------------------
__global__ void pack_all(const float* __restrict__ Wq1, const float* __restrict__ Wq2,
                         const float* __restrict__ Wk1, const float* __restrict__ Wk2,
                         const float* __restrict__ Wv,  const float* __restrict__ Wo,
                         bf16* __restrict__ tmp, bf16* __restrict__ w1,
                         bf16* __restrict__ wo) {
    const float* src; bf16* dst; int ld, col0;
    switch (blockIdx.y) {
        case 0:  src = Wq1; dst = tmp;                ld = DD;     col0 = 0;      break;
        case 1:  src = Wq2; dst = tmp + 1 * DD * DD;  ld = DD;     col0 = 0;      break;
        case 2:  src = Wk1; dst = tmp + 2 * DD * DD;  ld = DD;     col0 = 0;      break;
        case 3:  src = Wk2; dst = tmp + 3 * DD * DD;  ld = DD;     col0 = 0;      break;
        case 4:  src = Wv;  dst = w1;                 ld = 3 * DD; col0 = 2 * DD; break;
        default: src = Wo;  dst = wo;                 ld = DD;     col0 = 0;      break;
    }
    int idx = blockIdx.x * 256 + threadIdx.x;
    int r = idx >> 8;
    int c = (idx & 255) * 4;
    float4 v = *(const float4*)(src + r * 1024 + c);
    bf16* d = dst + (size_t)r * ld + col0 + c;
    *(__nv_bfloat162*)(d)     = __floats2bfloat162_rn(v.x, v.y);
    *(__nv_bfloat162*)(d + 2) = __floats2bfloat162_rn(v.z, v.w);
}

// ---------------------------------------------------------------------------
// adaLN matvecs: 32 outputs/block, 8-way K-split (128 iters/thread).
// fc1: h = silu(emb) @ Wada1            grid (32, 2)
// fc2: ada = h @ Wada2 + bias           grid (64, 2)
// ---------------------------------------------------------------------------
__global__ void ada_fc1(const float* __restrict__ emb, const float* __restrict__ W,
                        float* __restrict__ h) {
    const int b  = blockIdx.y;
    const int o0 = blockIdx.x * 32;
    const int tid = threadIdx.x;
    __shared__ float se[DD];
    __shared__ float part[256];

    for (int i = tid; i < DD; i += 256) {
        float e = emb[b * DD + i];
        se[i] = e / (1.0f + expf(-e));
    }
    __syncthreads();

    const int o  = o0 + (tid & 31);
    const int kq = tid >> 5;                  // 0..7
    const float* wp = W + (size_t)(kq * 128) * DD + o;
    const float* sp = se + kq * 128;
    float acc = 0.0f;
    #pragma unroll 8
    for (int k = 0; k < 128; k++) acc += sp[k] * wp[(size_t)k * DD];
    part[tid] = acc;
    __syncthreads();
    if (tid < 32) {
        float s = 0.0f;
        #pragma unroll
        for (int j = 0; j < 8; j++) s += part[tid + 32 * j];
        h[b * DD + o0 + tid] = s;
    }
}

__global__ void ada_fc2(const float* __restrict__ h, const float* __restrict__ W,
                        const float* __restrict__ bias, float* __restrict__ ada) {
    const int b  = blockIdx.y;
    const int o0 = blockIdx.x * 32;
    const int tid = threadIdx.x;
    __shared__ float sh[DD];
    __shared__ float part[256];

    for (int i = tid; i < DD; i += 256) sh[i] = h[b * DD + i];
    __syncthreads();

    const int o  = o0 + (tid & 31);
    const int kq = tid >> 5;
    const float* wp = W + (size_t)(kq * 128) * (2 * DD) + o;
    const float* sp = sh + kq * 128;
    float acc = 0.0f;
    #pragma unroll 8
    for (int k = 0; k < 128; k++) acc += sp[k] * wp[(size_t)k * (2 * DD)];
    part[tid] = acc;
    __syncthreads();
    if (tid < 32) {
        float s = bias[o0 + tid];
        #pragma unroll
        for (int j = 0; j < 8; j++) s += part[tid + 32 * j];
        ada[b * 2 * DD + o0 + tid] = s;
    }
}

// ---------------------------------------------------------------------------
// LayerNorm + adaLN scale/shift -> bf16
// ---------------------------------------------------------------------------
__global__ void ln_mod(const float* __restrict__ x, const float* __restrict__ ada,
                       bf16* __restrict__ xn) {
    int row = blockIdx.x;
    int b = row >> 11;
    int tid = threadIdx.x;
    const float* xr = x + (size_t)row * DD;

    float4 xv = *(const float4*)(xr + tid * 4);
    float s  = xv.x + xv.y + xv.z + xv.w;
    float s2 = xv.x * xv.x + xv.y * xv.y + xv.z * xv.z + xv.w * xv.w;
    #pragma unroll
    for (int off = 16; off; off >>= 1) {
        s  += __shfl_xor_sync(0xffffffffu, s,  off);
        s2 += __shfl_xor_sync(0xffffffffu, s2, off);
    }
    __shared__ float rs[8], rs2[8];
    int wid = tid >> 5, lane = tid & 31;
    if (lane == 0) { rs[wid] = s; rs2[wid] = s2; }
    __syncthreads();
    float S = 0.f, S2 = 0.f;
    #pragma unroll
    for (int w = 0; w < 8; w++) { S += rs[w]; S2 += rs2[w]; }
    float mu  = S * (1.0f / DD);
    float var = S2 * (1.0f / DD) - mu * mu;
    float rinv = rsqrtf(var + 1e-6f);

    int c = tid * 4;
    float4 sc  = *(const float4*)(ada + b * 2 * DD + DD + c);
    float4 shv = *(const float4*)(ada + b * 2 * DD + c);
    float o0 = (xv.x - mu) * rinv * (1.0f + sc.x) + shv.x;
    float o1 = (xv.y - mu) * rinv * (1.0f + sc.y) + shv.y;
    float o2 = (xv.z - mu) * rinv * (1.0f + sc.z) + shv.z;
    float o3 = (xv.w - mu) * rinv * (1.0f + sc.w) + shv.w;
    uint2 st;
    st.x = packbf(o0, o1);
    st.y = packbf(o2, o3);
    *(uint2*)(xn + (size_t)row * DD + c) = st;
}

// ---------------------------------------------------------------------------
// Shared GEMM tile parameters
// ---------------------------------------------------------------------------
#define ASTR 40    // halves: 32 + 8 pad
#define BSTR 136   // halves: 128 + 8 pad
#define GSTAGES 4
#define GEMM_SMEM (GSTAGES * (128 * ASTR + 32 * BSTR) * 2)

// ---------------------------------------------------------------------------
// Weight-combine GEMM: Wq12 = bWq1 @ bWq2, Wk12 = bWk1 @ bWk2  (M=N=K=1024)
// 128x64 tiles -> grid (32, 8) = 256 CTAs (vs 128 before: fills all SMs,
// 2 CTAs/SM latency hiding). Warp tile 64x16 (2x4 warps).
// ---------------------------------------------------------------------------
#define BSTR2 72   // halves: 64 + 8 pad
#define WG_SMEM (GSTAGES * (128 * ASTR + 32 * BSTR2) * 2)

__global__ __launch_bounds__(256, 2)
void wgemm(const bf16* __restrict__ T, bf16* __restrict__ w1) {
    extern __shared__ bf16 smg[];
    bf16* Asm = smg;
    bf16* Bsm = smg + GSTAGES * 128 * ASTR;

    const int mat  = blockIdx.x >> 4;
    const int coln = (blockIdx.x & 15) * 64;
    const int bm   = blockIdx.y * 128;
    const bf16* A = T + (size_t)mat * 2 * DD * DD;            // Wq1 or Wk1
    const bf16* B = T + (size_t)mat * 2 * DD * DD + DD * DD;  // Wq2 or Wk2

    const int tid = threadIdx.x;
    const int warp = tid >> 5, lane = tid & 31;
    const int gid = lane >> 2, tig = lane & 3;
    const int wm = (warp >> 2) * 64;
    const int wn = (warp & 3) * 16;

    float acc[4][2][4];
    #pragma unroll
    for (int mi = 0; mi < 4; mi++)
        #pragma unroll
        for (int ni = 0; ni < 2; ni++)
            #pragma unroll
            for (int r = 0; r < 4; r++) acc[mi][ni][r] = 0.0f;

    auto issue = [&](int st, int k0) {
        bf16* as = Asm + st * 128 * ASTR;
        bf16* bs = Bsm + st * 32 * BSTR2;
        #pragma unroll
        for (int i = 0; i < 2; i++) {
            int idx = tid + i * 256;
            int ar = idx >> 2, ach = idx & 3;
            cp16(&as[ar * ASTR + ach * 8],
                 &A[(size_t)(bm + ar) * DD + k0 + ach * 8]);
        }
        // B tile: 32 rows x 64 cols = 256 chunks of 8 halves, 1 per thread
        int br = tid >> 3, bc = tid & 7;
        cp16(&bs[br * BSTR2 + bc * 8],
             &B[(size_t)(k0 + br) * DD + coln + bc * 8]);
    };

    #pragma unroll
    for (int s = 0; s < 3; s++) { issue(s, s * 32); CP_COMMIT; }

    for (int kt = 0; kt < DD / 32; kt++) {
        CP_WAIT(2);
        __syncthreads();
        if (kt + 3 < DD / 32) issue((kt + 3) & 3, (kt + 3) * 32);
        CP_COMMIT;

        const bf16* as = Asm + (kt & 3) * 128 * ASTR;
        const bf16* bs = Bsm + (kt & 3) * 32 * BSTR2;
        #pragma unroll
        for (int kk = 0; kk < 2; kk++) {
            unsigned af[4][4], bfg[2][2];
            #pragma unroll
            for (int mi = 0; mi < 4; mi++) {
                int row = wm + mi * 16 + (lane & 15);
                int col = kk * 16 + 8 * (lane >> 4);
                ldsm_x4(af[mi][0], af[mi][1], af[mi][2], af[mi][3],
                        &as[row * ASTR + col]);
            }
            {
                int row = kk * 16 + (lane & 7) + 8 * ((lane >> 3) & 1);
                int col = wn + 8 * (lane >> 4);
                unsigned r0, r1, r2, r3;
                ldsm_x4t(r0, r1, r2, r3, &bs[row * BSTR2 + col]);
                bfg[0][0] = r0; bfg[0][1] = r1;
                bfg[1][0] = r2; bfg[1][1] = r3;
            }
            #pragma unroll
            for (int mi = 0; mi < 4; mi++)
                #pragma unroll
                for (int ni = 0; ni < 2; ni++)
                    mma_bf16(acc[mi][ni], af[mi], bfg[ni]);
        }
    }

    bf16* dst = w1 + (size_t)mat * DD;   // seg column offset in [1024][3072]
    #pragma unroll
    for (int mi = 0; mi < 4; mi++) {
        #pragma unroll
        for (int ni = 0; ni < 2; ni++) {
            int col = coln + wn + ni * 8 + 2 * tig;
            #pragma unroll
            for (int half = 0; half < 2; half++) {
                int row = bm + wm + mi * 16 + gid + half * 8;
                *(unsigned*)(dst + (size_t)row * (3 * DD) + col) =
                    packbf(acc[mi][ni][half * 2], acc[mi][ni][half * 2 + 1]);
            }
        }
    }
}

// ---------------------------------------------------------------------------
// Fused QKV GEMM + RoPE: [q|k|v] = xn @ [Wq12|Wk12|Wv], RoPE on q/k segs.
// grid (24, 32). Warp tile 32x64 (head-aligned).
// ---------------------------------------------------------------------------
__global__ __launch_bounds__(256, 2)
void qkv_rope(const bf16* __restrict__ A, const bf16* __restrict__ B,
              const float* __restrict__ rope,
              bf16* __restrict__ Cq, bf16* __restrict__ Ck,
              bf16* __restrict__ Cv) {
    extern __shared__ bf16 smg[];
    bf16* Asm = smg;
    bf16* Bsm = smg + GSTAGES * 128 * ASTR;

    const int bm = blockIdx.y * 128;
    const int bn = blockIdx.x * 128;
    const int seg = bn >> 10;
    const int coln = bn & 1023;

    const int tid = threadIdx.x;
    const int warp = tid >> 5, lane = tid & 31;
    const int gid = lane >> 2, tig = lane & 3;
    const int wm = (warp & 3) * 32;    // 4 row groups of 32
    const int wn = (warp >> 2) * 64;   // 2 col groups of 64 (head-aligned)

    float acc[2][8][4];
    #pragma unroll
    for (int mi = 0; mi < 2; mi++)
        #pragma unroll
        for (int ni = 0; ni < 8; ni++)
            #pragma unroll
            for (int r = 0; r < 4; r++) acc[mi][ni][r] = 0.0f;

    auto issue = [&](int st, int k0) {
        bf16* as = Asm + st * 128 * ASTR;
        bf16* bs = Bsm + st * 32 * BSTR;
        #pragma unroll
        for (int i = 0; i < 2; i++) {
            int idx = tid + i * 256;
            int ar = idx >> 2, ach = idx & 3;
            cp16(&as[ar * ASTR + ach * 8],
                 &A[(size_t)(bm + ar) * DD + k0 + ach * 8]);
            int br = idx >> 4, bch = idx & 15;
            cp16(&bs[br * BSTR + bch * 8],
                 &B[(size_t)(k0 + br) * (3 * DD) + bn + bch * 8]);
        }
    };

    #pragma unroll
    for (int s = 0; s < 3; s++) { issue(s, s * 32); CP_COMMIT; }

    for (int kt = 0; kt < DD / 32; kt++) {
        CP_WAIT(2);
        __syncthreads();
        if (kt + 3 < DD / 32) issue((kt + 3) & 3, (kt + 3) * 32);
        CP_COMMIT;

        const bf16* as = Asm + (kt & 3) * 128 * ASTR;
        const bf16* bs = Bsm + (kt & 3) * 32 * BSTR;
        #pragma unroll
        for (int kk = 0; kk < 2; kk++) {
            unsigned af[2][4], bfg[8][2];
            #pragma unroll
            for (int mi = 0; mi < 2; mi++) {
                int row = wm + mi * 16 + (lane & 15);
                int col = kk * 16 + 8 * (lane >> 4);
                ldsm_x4(af[mi][0], af[mi][1], af[mi][2], af[mi][3],
                        &as[row * ASTR + col]);
            }
            #pragma unroll
            for (int nj = 0; nj < 4; nj++) {
                int row = kk * 16 + (lane & 7) + 8 * ((lane >> 3) & 1);
                int col = wn + nj * 16 + 8 * (lane >> 4);
                unsigned r0, r1, r2, r3;
                ldsm_x4t(r0, r1, r2, r3, &bs[row * BSTR + col]);
                bfg[nj * 2][0] = r0; bfg[nj * 2][1] = r1;
                bfg[nj * 2 + 1][0] = r2; bfg[nj * 2 + 1][1] = r3;
            }
            #pragma unroll
            for (int mi = 0; mi < 2; mi++)
                #pragma unroll
                for (int ni = 0; ni < 8; ni++)
                    mma_bf16(acc[mi][ni], af[mi], bfg[ni]);
        }
    }

    if (seg == 2) {
        #pragma unroll
        for (int mi = 0; mi < 2; mi++) {
            #pragma unroll
            for (int ni = 0; ni < 8; ni++) {
                int col = coln + wn + ni * 8 + 2 * tig;
                #pragma unroll
                for (int half = 0; half < 2; half++) {
                    int row = bm + wm + mi * 16 + gid + half * 8;
                    *(unsigned*)(Cv + (size_t)row * DD + col) =
                        packbf(acc[mi][ni][half * 2], acc[mi][ni][half * 2 + 1]);
                }
            }
        }
    } else {
        bf16* Cb = (seg == 0) ? Cq : Ck;
        #pragma unroll
        for (int mi = 0; mi < 2; mi++) {
            #pragma unroll
            for (int half = 0; half < 2; half++) {
                int row = bm + wm + mi * 16 + gid + half * 8;
                int n = row & (NN - 1);
                const float* rp = rope + (size_t)n * HD;
                #pragma unroll
                for (int ni = 0; ni < 4; ni++) {
                    int d0 = ni * 8 + 2 * tig;     // in-head index < 32
                    float lo0 = acc[mi][ni][half * 2 + 0];
                    float lo1 = acc[mi][ni][half * 2 + 1];
                    float hi0 = acc[mi][ni + 4][half * 2 + 0];
                    float hi1 = acc[mi][ni + 4][half * 2 + 1];
                    float c10, s10, c11, s11, c20, s20, c21, s21;
                    __sincosf(rp[d0],      &s10, &c10);
                    __sincosf(rp[d0 + 1],  &s11, &c11);
                    __sincosf(rp[d0 + 32], &s20, &c20);
                    __sincosf(rp[d0 + 33], &s21, &c21);
                    float q_lo0 = lo0 * c10 - hi0 * s10;
                    float q_lo1 = lo1 * c11 - hi1 * s11;
                    float q_hi0 = hi0 * c20 + lo0 * s20;
                    float q_hi1 = hi1 * c21 + lo1 * s21;
                    int gc = coln + wn + d0;
                    *(unsigned*)(Cb + (size_t)row * DD + gc)      = packbf(q_lo0, q_lo1);
                    *(unsigned*)(Cb + (size_t)row * DD + gc + 32) = packbf(q_hi0, q_hi1);
                }
            }
        }
    }
}

// ---------------------------------------------------------------------------
// Output GEMM: out = x + gate * (ao @ Wo).  64x32 warp tiles, fp32 epilogue.
// ---------------------------------------------------------------------------
__global__ __launch_bounds__(256, 2)
void tgemm_out(const bf16* __restrict__ A, const bf16* __restrict__ B,
               float* __restrict__ Cf, const float* __restrict__ X,
               const float* __restrict__ gate) {
    extern __shared__ bf16 smg[];
    bf16* Asm = smg;
    bf16* Bsm = smg + GSTAGES * 128 * ASTR;

    const int bm = blockIdx.y * 128;
    const int bn = blockIdx.x * 128;

    const int tid = threadIdx.x;
    const int warp = tid >> 5, lane = tid & 31;
    const int gid = lane >> 2, tig = lane & 3;
    const int wm = (warp >> 2) * 64;
    const int wn = (warp & 3) * 32;

    float acc[4][4][4];
    #pragma unroll
    for (int mi = 0; mi < 4; mi++)
        #pragma unroll
        for (int ni = 0; ni < 4; ni++)
            #pragma unroll
            for (int r = 0; r < 4; r++) acc[mi][ni][r] = 0.0f;

    auto issue = [&](int st, int k0) {
        bf16* as = Asm + st * 128 * ASTR;
        bf16* bs = Bsm + st * 32 * BSTR;
        #pragma unroll
        for (int i = 0; i < 2; i++) {
            int idx = tid + i * 256;
            int ar = idx >> 2, ach = idx & 3;
            cp16(&as[ar * ASTR + ach * 8],
                 &A[(size_t)(bm + ar) * DD + k0 + ach * 8]);
            int br = idx >> 4, bch = idx & 15;
            cp16(&bs[br * BSTR + bch * 8],
                 &B[(size_t)(k0 + br) * DD + bn + bch * 8]);
        }
    };

    #pragma unroll
    for (int s = 0; s < 3; s++) { issue(s, s * 32); CP_COMMIT; }

    for (int kt = 0; kt < DD / 32; kt++) {
        CP_WAIT(2);
        __syncthreads();
        if (kt + 3 < DD / 32) issue((kt + 3) & 3, (kt + 3) * 32);
        CP_COMMIT;

        const bf16* as = Asm + (kt & 3) * 128 * ASTR;
        const bf16* bs = Bsm + (kt & 3) * 32 * BSTR;
        #pragma unroll
        for (int kk = 0; kk < 2; kk++) {
            unsigned af[4][4], bfg[4][2];
            #pragma unroll
            for (int mi = 0; mi < 4; mi++) {
                int row = wm + mi * 16 + (lane & 15);
                int col = kk * 16 + 8 * (lane >> 4);
                ldsm_x4(af[mi][0], af[mi][1], af[mi][2], af[mi][3],
                        &as[row * ASTR + col]);
            }
            #pragma unroll
            for (int nj = 0; nj < 2; nj++) {
                int row = kk * 16 + (lane & 7) + 8 * ((lane >> 3) & 1);
                int col = wn + nj * 16 + 8 * (lane >> 4);
                unsigned r0, r1, r2, r3;
                ldsm_x4t(r0, r1, r2, r3, &bs[row * BSTR + col]);
                bfg[nj * 2][0] = r0; bfg[nj * 2][1] = r1;
                bfg[nj * 2 + 1][0] = r2; bfg[nj * 2 + 1][1] = r3;
            }
            #pragma unroll
            for (int mi = 0; mi < 4; mi++)
                #pragma unroll
                for (int ni = 0; ni < 4; ni++)
                    mma_bf16(acc[mi][ni], af[mi], bfg[ni]);
        }
    }

    #pragma unroll
    for (int mi = 0; mi < 4; mi++) {
        #pragma unroll
        for (int ni = 0; ni < 4; ni++) {
            int col = bn + wn + ni * 8 + 2 * tig;
            #pragma unroll
            for (int half = 0; half < 2; half++) {
                int row = bm + wm + mi * 16 + gid + half * 8;
                int bidx = row >> 11;
                float2 xv = *(const float2*)(X + (size_t)row * DD + col);
                float2 gv = *(const float2*)(gate + bidx * DD + col);
                float2 r;
                r.x = xv.x + gv.x * acc[mi][ni][half * 2 + 0];
                r.y = xv.y + gv.y * acc[mi][ni][half * 2 + 1];
                *(float2*)(Cf + (size_t)row * DD + col) = r;
            }
        }
    }
}

// ---------------------------------------------------------------------------
// Flash attention, bf16 mma. grid (N/128, H, B), 256 threads (8 warps).
// 128-row Q tile, 3-stage KV ring, P in registers, exp2 softmax with
// skip-rescale when the running max is unchanged.
// ---------------------------------------------------------------------------
#define QSTR 72
#define ATTN_SMEM ((128 * QSTR + 6 * 64 * QSTR) * 2)
#define SOFTMAX_SCALE 0.18033688f   // 0.125 * log2(e)

__global__ __launch_bounds__(256, 2)
void attn_kernel(const bf16* __restrict__ q, const bf16* __restrict__ k,
                 const bf16* __restrict__ v, bf16* __restrict__ o) {
    extern __shared__ bf16 sma[];
    bf16* Qs  = sma;
    bf16* KVs = sma + 128 * QSTR;

    const int qt = blockIdx.x, h = blockIdx.y, b = blockIdx.z;
    const int tid = threadIdx.x;
    const int warp = tid >> 5, lane = tid & 31;
    const int gid = lane >> 2, tig = lane & 3;
    const int hoff = h * HD;
    const size_t bbase = (size_t)b * NN * DD;

    auto issue_kv = [&](int kt, int st) {
        bf16* Ks = KVs + st * 2 * 64 * QSTR;
        bf16* Vs = Ks + 64 * QSTR;
        #pragma unroll
        for (int i = 0; i < 2; i++) {
            int idx = tid + i * 256;
            int r = idx >> 3, ch = idx & 7;
            size_t g = bbase + (size_t)(kt * 64 + r) * DD + hoff + ch * 8;
            cp16(&Ks[r * QSTR + ch * 8], &k[g]);
            cp16(&Vs[r * QSTR + ch * 8], &v[g]);
        }
    };

    #pragma unroll
    for (int i = 0; i < 4; i++) {
        int idx = tid + i * 256;
        int r = idx >> 3, ch = idx & 7;
        cp16(&Qs[r * QSTR + ch * 8],
             &q[bbase + (size_t)(qt * 128 + r) * DD + hoff + ch * 8]);
    }
    issue_kv(0, 0);
    CP_COMMIT;
    issue_kv(1, 1);
    CP_COMMIT;

    unsigned qa[4][4];
    float m_i[2] = {-1e30f, -1e30f};
    float l_i[2] = {0.0f, 0.0f};
    float O[8][4];
    #pragma unroll
    for (int ni = 0; ni < 8; ni++)
        #pragma unroll
        for (int r = 0; r < 4; r++) O[ni][r] = 0.0f;

    for (int kt = 0; kt < NN / 64; kt++) {
        CP_WAIT(1);
        __syncthreads();
        if (kt + 2 < NN / 64) issue_kv(kt + 2, (kt + 2) % 3);
        CP_COMMIT;

        if (kt == 0) {
            #pragma unroll
            for (int kk = 0; kk < 4; kk++) {
                int row = warp * 16 + (lane & 15);
                int col = kk * 16 + 8 * (lane >> 4);
                ldsm_x4(qa[kk][0], qa[kk][1], qa[kk][2], qa[kk][3],
                        &Qs[row * QSTR + col]);
            }
        }

        const bf16* ks = KVs + (kt % 3) * 2 * 64 * QSTR;
        const bf16* vs = ks + 64 * QSTR;

        float S[8][4];
        #pragma unroll
        for (int ni = 0; ni < 8; ni++)
            #pragma unroll
            for (int r = 0; r < 4; r++) S[ni][r] = 0.0f;
        #pragma unroll
        for (int kk = 0; kk < 4; kk++) {
            #pragma unroll
            for (int nj = 0; nj < 4; nj++) {
                int row = nj * 16 + (lane & 7) + 8 * (lane >> 4);
                int col = kk * 16 + 8 * ((lane >> 3) & 1);
                unsigned r0, r1, r2, r3;
                ldsm_x4(r0, r1, r2, r3, &ks[row * QSTR + col]);
                unsigned b0[2] = {r0, r1}, b1[2] = {r2, r3};
                mma_bf16(S[nj * 2],     qa[kk], b0);
                mma_bf16(S[nj * 2 + 1], qa[kk], b1);
            }
        }
        #pragma unroll
        for (int ni = 0; ni < 8; ni++)
            #pragma unroll
            for (int r = 0; r < 4; r++) S[ni][r] *= SOFTMAX_SCALE;

        // online softmax in exp2 domain; skip O-rescale when max unchanged
        #pragma unroll
        for (int half = 0; half < 2; half++) {
            float mx = -1e30f;
            #pragma unroll
            for (int ni = 0; ni < 8; ni++)
                mx = fmaxf(mx, fmaxf(S[ni][half * 2], S[ni][half * 2 + 1]));
            mx = fmaxf(mx, __shfl_xor_sync(0xffffffffu, mx, 1));
            mx = fmaxf(mx, __shfl_xor_sync(0xffffffffu, mx, 2));
            float fac = 1.0f;
            if (mx > m_i[half]) {
                fac = exp2f(m_i[half] - mx);
                m_i[half] = mx;
                #pragma unroll
                for (int ni = 0; ni < 8; ni++) {
                    O[ni][half * 2]     *= fac;
                    O[ni][half * 2 + 1] *= fac;
                }
            }
            float mnew = m_i[half];
            float rs = 0.0f;
            #pragma unroll
            for (int ni = 0; ni < 8; ni++) {
                float p0 = exp2f(S[ni][half * 2]     - mnew);
                float p1 = exp2f(S[ni][half * 2 + 1] - mnew);
                S[ni][half * 2]     = p0;
                S[ni][half * 2 + 1] = p1;
                rs += p0 + p1;
            }
            rs += __shfl_xor_sync(0xffffffffu, rs, 1);
            rs += __shfl_xor_sync(0xffffffffu, rs, 2);
            l_i[half] = l_i[half] * fac + rs;
        }

        unsigned pa[4][4];
        #pragma unroll
        for (int kk2 = 0; kk2 < 4; kk2++) {
            pa[kk2][0] = packbf(S[2 * kk2][0],     S[2 * kk2][1]);
            pa[kk2][1] = packbf(S[2 * kk2][2],     S[2 * kk2][3]);
            pa[kk2][2] = packbf(S[2 * kk2 + 1][0], S[2 * kk2 + 1][1]);
            pa[kk2][3] = packbf(S[2 * kk2 + 1][2], S[2 * kk2 + 1][3]);
        }

        #pragma unroll
        for (int kk2 = 0; kk2 < 4; kk2++) {
            #pragma unroll
            for (int nj = 0; nj < 4; nj++) {
                int row = kk2 * 16 + (lane & 7) + 8 * ((lane >> 3) & 1);
                int col = nj * 16 + 8 * (lane >> 4);
                unsigned r0, r1, r2, r3;
                ldsm_x4t(r0, r1, r2, r3, &vs[row * QSTR + col]);
                unsigned b0[2] = {r0, r1}, b1[2] = {r2, r3};
                mma_bf16(O[nj * 2],     pa[kk2], b0);
                mma_bf16(O[nj * 2 + 1], pa[kk2], b1);
            }
        }
    }

    float inv0 = 1.0f / l_i[0], inv1 = 1.0f / l_i[1];
    #pragma unroll
    for (int ni = 0; ni < 8; ni++) {
        int col = hoff + ni * 8 + 2 * tig;
        int row0 = qt * 128 + warp * 16 + gid;
        *(unsigned*)(o + bbase + (size_t)row0 * DD + col) =
            packbf(O[ni][0] * inv0, O[ni][1] * inv0);
        *(unsigned*)(o + bbase + (size_t)(row0 + 8) * DD + col) =
            packbf(O[ni][2] * inv1, O[ni][3] * inv1);
    }
}

// ---------------------------------------------------------------------------
// Launcher (R15 ordering: pack -> wgemm -> ada -> ln -> qkv -> attn -> out)
// ---------------------------------------------------------------------------
extern "C" void kernel_launch(void* const* d_in, const int* in_sizes, int n_in,
                              void* d_out, int out_size) {
    const float* x     = (const float*)d_in[0];
    const float* emb   = (const float*)d_in[1];
    const float* gate  = (const float*)d_in[2];
    // d_in[3] = crossattn_emb: unused by the reference
    const float* rope  = (const float*)d_in[4];
    const float* Wq1   = (const float*)d_in[5];
    const float* Wq2   = (const float*)d_in[6];
    const float* Wk1   = (const float*)d_in[7];
    const float* Wk2   = (const float*)d_in[8];
    const float* Wv    = (const float*)d_in[9];
    const float* Wo    = (const float*)d_in[10];
    const float* Wada1 = (const float*)d_in[11];
    const float* Wada2 = (const float*)d_in[12];
    const float* bada2 = (const float*)d_in[13];
    float* out = (float*)d_out;

    bf16 *xn_p, *tmp_p, *q_p, *k_p, *v_p, *ao_p, *w1_p, *wo_p;
    float *h_p, *ada_p;
    cudaGetSymbolAddress((void**)&xn_p,  g_xn);
    cudaGetSymbolAddress((void**)&tmp_p, g_tmp);
    cudaGetSymbolAddress((void**)&q_p,   g_q);
    cudaGetSymbolAddress((void**)&k_p,   g_k);
    cudaGetSymbolAddress((void**)&v_p,   g_v);
    cudaGetSymbolAddress((void**)&ao_p,  g_ao);
    cudaGetSymbolAddress((void**)&h_p,   g_h);
    cudaGetSymbolAddress((void**)&ada_p, g_ada);
    cudaGetSymbolAddress((void**)&w1_p,  g_w1);
    cudaGetSymbolAddress((void**)&wo_p,  g_wo);

    cudaFuncSetAttribute(wgemm,     cudaFuncAttributeMaxDynamicSharedMemorySize, WG_SMEM);
    cudaFuncSetAttribute(qkv_rope,  cudaFuncAttributeMaxDynamicSharedMemorySize, GEMM_SMEM);
    cudaFuncSetAttribute(tgemm_out, cudaFuncAttributeMaxDynamicSharedMemorySize, GEMM_SMEM);
    cudaFuncSetAttribute(attn_kernel, cudaFuncAttributeMaxDynamicSharedMemorySize, ATTN_SMEM);

    // pack weights -> bf16 staging (+ Wv, Wo into final layouts)
    pack_all<<<dim3(1024, 6), 256>>>(Wq1, Wq2, Wk1, Wk2, Wv, Wo,
                                     tmp_p, w1_p, wo_p);

    // combine stacked projections: w1 seg0 = Wq1@Wq2, seg1 = Wk1@Wk2
    wgemm<<<dim3(32, 8), 256, WG_SMEM>>>(tmp_p, w1_p);

    // adaLN modulation (8-way K-split matvecs)
    ada_fc1<<<dim3(32, 2), 256>>>(emb, Wada1, h_p);
    ada_fc2<<<dim3(64, 2), 256>>>(h_p, Wada2, bada2, ada_p);

    // LayerNorm + scale/shift -> bf16
    ln_mod<<<MM, 256>>>(x, ada_p, xn_p);

    // Fused QKV projection + RoPE: [q|k|v] = xn @ [Wq12|Wk12|Wv]
    qkv_rope<<<dim3(24, 32), 256, GEMM_SMEM>>>(xn_p, w1_p, rope,
                                               q_p, k_p, v_p);

    // Attention (128-row Q tiles, 3-stage KV pipeline, 2 CTAs/SM)
    attn_kernel<<<dim3(NN / 128, HH, BB), 256, ATTN_SMEM>>>(q_p, k_p, v_p, ao_p);

    // Output GEMM: out = x + gate * (ao @ Wo)
    tgemm_out<<<dim3(8, 32), 256, GEMM_SMEM>>>(ao_p, wo_p, out, x, gate);
}